// round 5
// baseline (speedup 1.0000x reference)
#include <cuda_runtime.h>
#include <cuda_fp16.h>
#include <math.h>

#define NN   50000
#define EE   1600000
#define EP   (EE + NN)
#define GG   64
#define DIN  128
#define HID  64
#define HH1  4
#define F1   (HH1 * HID)   // 256
#define F2   HID           // 64
#define NEG_SLOPE 0.2f
#define BN_EPS 1e-5f

// ---------------- device scratch ----------------
__device__ __half g_xw1h[(size_t)NN * F1];   // 25.6 MB fp16 gather table (layer 1)
__device__ __half g_xw2h[(size_t)NN * F2];   // 6.4 MB fp16 gather table (layer 2)
__device__ float  g_as1[NN * HH1], g_ad1[NN * HH1];
__device__ float  g_as2[NN], g_ad2[NN];
__device__ int    g_deg[NN];
__device__ int    g_rowptr[NN + 1];
__device__ int    g_cursor[NN];
__device__ int    g_colsrc[EP];
__device__ float  g_gsum[GG * F2];
__device__ float  g_gcnt[GG];

// ---------------- CSR build + init ----------------
__global__ void init_kernel() {
    int i = blockIdx.x * blockDim.x + threadIdx.x;
    if (i < NN) g_deg[i] = 1;                 // self loop
    if (i < GG * F2) g_gsum[i] = 0.f;
    if (i < GG) g_gcnt[i] = 0.f;
}

__global__ void count_kernel(const int* __restrict__ ei, const int* __restrict__ batch) {
    int i = blockIdx.x * blockDim.x + threadIdx.x;
    if (i < EE) atomicAdd(&g_deg[ei[EE + i]], 1);
    if (i < NN) atomicAdd(&g_gcnt[batch[i]], 1.0f);
}

__global__ void scan_kernel() {
    __shared__ int sums[1024];
    const int T = 1024;
    int tid = threadIdx.x;
    int chunk = (NN + T - 1) / T;
    int begin = tid * chunk;
    int end = min(begin + chunk, NN);
    int s = 0;
    for (int i = begin; i < end; i++) s += g_deg[i];
    sums[tid] = s;
    __syncthreads();
    for (int off = 1; off < T; off <<= 1) {
        int v = 0;
        if (tid >= off) v = sums[tid - off];
        __syncthreads();
        sums[tid] += v;
        __syncthreads();
    }
    int run = sums[tid] - s;
    for (int i = begin; i < end; i++) {
        g_rowptr[i] = run;
        g_cursor[i] = run;
        run += g_deg[i];
    }
    if (tid == T - 1) g_rowptr[NN] = EP;
}

__global__ void fill_kernel(const int* __restrict__ ei) {
    int i = blockIdx.x * blockDim.x + threadIdx.x;
    if (i >= EP) return;
    int s, d;
    if (i < EE) { s = ei[i]; d = ei[EE + i]; }
    else        { s = d = i - EE; }
    int pos = atomicAdd(&g_cursor[d], 1);
    g_colsrc[pos] = s;
}

// ---------------- SGEMM1: 128x64 tile, 8x4/thread, fused fp16-store + alpha epilogue ----
__global__ void sgemm1_kernel(const float* __restrict__ A, const float* __restrict__ B,
                              __half* __restrict__ Ch,
                              const float* __restrict__ att_src,
                              const float* __restrict__ att_dst,
                              float* __restrict__ as_, float* __restrict__ ad_) {
    const int M = NN, Nn = F1, K = DIN;
    __shared__ float As[16][132];
    __shared__ float Bs[16][64];
    const int t  = threadIdx.x;     // 256
    const int tx = t & 15;
    const int ty = t >> 4;
    const int rb = blockIdx.y * 128;
    const int cb = blockIdx.x * 64;
    const int head = blockIdx.x;

    float acc[8][4] = {};

    for (int k0 = 0; k0 < K; k0 += 16) {
        #pragma unroll
        for (int r = 0; r < 2; r++) {
            int idx = t + r * 256;
            int row = idx >> 2;
            int kq  = (idx & 3) * 4;
            float4 v = make_float4(0.f, 0.f, 0.f, 0.f);
            int gr = rb + row;
            if (gr < M) v = *(const float4*)&A[(size_t)gr * K + k0 + kq];
            As[kq + 0][row] = v.x; As[kq + 1][row] = v.y;
            As[kq + 2][row] = v.z; As[kq + 3][row] = v.w;
        }
        {
            int brow = t >> 4, bcol = (t & 15) * 4;
            *(float4*)&Bs[brow][bcol] =
                *(const float4*)&B[(size_t)(k0 + brow) * Nn + cb + bcol];
        }
        __syncthreads();
        #pragma unroll
        for (int kk = 0; kk < 16; kk++) {
            float a[8];
            *(float4*)&a[0] = *(float4*)&As[kk][ty * 8];
            *(float4*)&a[4] = *(float4*)&As[kk][ty * 8 + 4];
            float4 b = *(float4*)&Bs[kk][tx * 4];
            #pragma unroll
            for (int i = 0; i < 8; i++) {
                acc[i][0] += a[i] * b.x;
                acc[i][1] += a[i] * b.y;
                acc[i][2] += a[i] * b.z;
                acc[i][3] += a[i] * b.w;
            }
        }
        __syncthreads();
    }

    float4 asv = *(const float4*)&att_src[head * 64 + tx * 4];
    float4 adv = *(const float4*)&att_dst[head * 64 + tx * 4];

    #pragma unroll
    for (int i = 0; i < 8; i++) {
        int row = rb + ty * 8 + i;
        bool ok = row < M;
        if (ok) {
            __half2* outp = (__half2*)&Ch[(size_t)row * Nn + cb + tx * 4];
            outp[0] = __floats2half2_rn(acc[i][0], acc[i][1]);
            outp[1] = __floats2half2_rn(acc[i][2], acc[i][3]);
        }
        float sp = acc[i][0] * asv.x + acc[i][1] * asv.y + acc[i][2] * asv.z + acc[i][3] * asv.w;
        float dp = acc[i][0] * adv.x + acc[i][1] * adv.y + acc[i][2] * adv.z + acc[i][3] * adv.w;
        #pragma unroll
        for (int off = 8; off; off >>= 1) {
            sp += __shfl_xor_sync(0xffffffffu, sp, off);
            dp += __shfl_xor_sync(0xffffffffu, dp, off);
        }
        if (tx == 0 && ok) {
            as_[row * HH1 + head] = sp;
            ad_[row * HH1 + head] = dp;
        }
    }
}

// ---------------- agg1 mega-kernel -------------------------------------------
// One 256-thread block per dst node:
//   phase 1: in-block online softmax stats over incoming edges (4 heads)
//   phase 2: weighted fp16 gather-aggregate (SMEM-staged weights)
//   epilogue: +bias1, BN, relu -> h1 row in SMEM
//             -> GEMV h1row @ W2 -> xw2 row (fp16 table) + alpha2 dots
__global__ __launch_bounds__(256) void agg1_kernel(
        const __half* __restrict__ xwh,
        const float* __restrict__ as_, const float* __restrict__ ad_,
        const float* __restrict__ bias,
        const float* __restrict__ bng, const float* __restrict__ bnb,
        const float* __restrict__ bnm, const float* __restrict__ bnv,
        const float* __restrict__ W2,
        const float* __restrict__ att_src2, const float* __restrict__ att_dst2,
        __half* __restrict__ xw2h, float* __restrict__ as2, float* __restrict__ ad2) {
    const int d   = blockIdx.x;
    const int tid = threadIdx.x;
    const int lane = tid & 31, wid = tid >> 5;

    __shared__ float warp_m[HH1][8], warp_s[HH1][8];
    __shared__ float smx[HH1], sinv[HH1];
    __shared__ float wsm[64 * HH1];
    __shared__ int   ssm[64];
    __shared__ float h1row[F1];
    __shared__ float gsh[4][F2];
    __shared__ float xw2row[F2];
    __shared__ float redsh[2][2];

    const int s0 = g_rowptr[d], s1 = g_rowptr[d + 1];

    // destination alpha (all 4 heads)
    float4 adv4 = *(const float4*)&ad_[(size_t)d * HH1];
    float adh[HH1] = {adv4.x, adv4.y, adv4.z, adv4.w};

    // ---- phase 1: online softmax stats ----
    float mx[HH1], sm[HH1];
    #pragma unroll
    for (int h = 0; h < HH1; h++) { mx[h] = -1e30f; sm[h] = 0.f; }
    for (int j = s0 + tid; j < s1; j += 256) {
        int s = g_colsrc[j];
        float4 av = *(const float4*)&as_[(size_t)s * HH1];
        float avh[HH1] = {av.x, av.y, av.z, av.w};
        #pragma unroll
        for (int h = 0; h < HH1; h++) {
            float e = avh[h] + adh[h];
            e = e >= 0.f ? e : NEG_SLOPE * e;
            float nm = fmaxf(mx[h], e);
            sm[h] = sm[h] * __expf(mx[h] - nm) + __expf(e - nm);
            mx[h] = nm;
        }
    }
    #pragma unroll
    for (int h = 0; h < HH1; h++) {
        #pragma unroll
        for (int off = 16; off; off >>= 1) {
            float mo = __shfl_xor_sync(0xffffffffu, mx[h], off);
            float so = __shfl_xor_sync(0xffffffffu, sm[h], off);
            float nm = fmaxf(mx[h], mo);
            sm[h] = sm[h] * __expf(mx[h] - nm) + so * __expf(mo - nm);
            mx[h] = nm;
        }
        if (!lane) { warp_m[h][wid] = mx[h]; warp_s[h][wid] = sm[h]; }
    }
    __syncthreads();
    if (tid < HH1) {
        float M = -1e30f, S = 0.f;
        #pragma unroll
        for (int w = 0; w < 8; w++) {
            float mo = warp_m[tid][w], so = warp_s[tid][w];
            float nm = fmaxf(M, mo);
            S = S * __expf(M - nm) + so * __expf(mo - nm);
            M = nm;
        }
        smx[tid] = M;
        sinv[tid] = 1.0f / (S + 1e-16f);
    }
    __syncthreads();

    // ---- phase 2: weighted aggregate ----
    float acc = 0.f;
    for (int base = s0; base < s1; base += 64) {
        int cnt = min(64, s1 - base);
        if (tid < cnt * HH1) {
            int e = tid >> 2, h = tid & 3;
            int s = g_colsrc[base + e];
            float ev = as_[s * HH1 + h] + adh[h];
            ev = ev >= 0.f ? ev : NEG_SLOPE * ev;
            wsm[e * HH1 + h] = __expf(ev - smx[h]) * sinv[h];
            if (h == 0) ssm[e] = s;
        }
        __syncthreads();
        int h = tid >> 6;
        #pragma unroll 4
        for (int e = 0; e < cnt; e++)
            acc += wsm[e * HH1 + h] * __half2float(xwh[(size_t)ssm[e] * F1 + tid]);
        __syncthreads();
    }

    // ---- epilogue: bias + BN + relu ----
    float o = acc + bias[tid];
    o = (o - bnm[tid]) * (bng[tid] * rsqrtf(bnv[tid] + BN_EPS)) + bnb[tid];
    o = fmaxf(o, 0.f);
    h1row[tid] = o;
    __syncthreads();

    // ---- fused layer-2 GEMV: xw2 = h1row @ W2  (W2: [256,64] row-major) ----
    {
        int j = tid & 63, p = tid >> 6;
        float part = 0.f;
        #pragma unroll 8
        for (int k = 0; k < 64; k++) {
            int kk = p * 64 + k;
            part += h1row[kk] * W2[kk * F2 + j];
        }
        gsh[p][j] = part;
    }
    __syncthreads();
    if (tid < F2) {
        float v = gsh[0][tid] + gsh[1][tid] + gsh[2][tid] + gsh[3][tid];
        xw2row[tid] = v;
        xw2h[(size_t)d * F2 + tid] = __float2half_rn(v);
    }
    __syncthreads();
    // alpha2 dots over 64 values (2 warps)
    if (tid < F2) {
        float v = xw2row[tid];
        float sv = v * att_src2[tid];
        float dv = v * att_dst2[tid];
        #pragma unroll
        for (int off = 16; off; off >>= 1) {
            sv += __shfl_xor_sync(0xffffffffu, sv, off);
            dv += __shfl_xor_sync(0xffffffffu, dv, off);
        }
        if (!lane) { redsh[wid][0] = sv; redsh[wid][1] = dv; }
    }
    __syncthreads();
    if (tid == 0) {
        as2[d] = redsh[0][0] + redsh[1][0];
        ad2[d] = redsh[0][1] + redsh[1][1];
    }
}

// ---------------- agg2 mega-kernel (64 threads/block) + fused pooling ----------
__global__ __launch_bounds__(64) void agg2_kernel(
        const __half* __restrict__ xwh,
        const float* __restrict__ as_, const float* __restrict__ ad_,
        const float* __restrict__ bias,
        const float* __restrict__ bng, const float* __restrict__ bnb,
        const float* __restrict__ bnm, const float* __restrict__ bnv,
        const int* __restrict__ batch) {
    const int d   = blockIdx.x;
    const int tid = threadIdx.x;
    const int lane = tid & 31, wid = tid >> 5;

    __shared__ float warp_m[2], warp_s[2];
    __shared__ float smx, sinv;
    __shared__ float wsm[64];
    __shared__ int   ssm[64];

    const int s0 = g_rowptr[d], s1 = g_rowptr[d + 1];
    const float adv = ad_[d];

    // phase 1: stats
    float mx = -1e30f, sm = 0.f;
    for (int j = s0 + tid; j < s1; j += 64) {
        float e = as_[g_colsrc[j]] + adv;
        e = e >= 0.f ? e : NEG_SLOPE * e;
        float nm = fmaxf(mx, e);
        sm = sm * __expf(mx - nm) + __expf(e - nm);
        mx = nm;
    }
    #pragma unroll
    for (int off = 16; off; off >>= 1) {
        float mo = __shfl_xor_sync(0xffffffffu, mx, off);
        float so = __shfl_xor_sync(0xffffffffu, sm, off);
        float nm = fmaxf(mx, mo);
        sm = sm * __expf(mx - nm) + so * __expf(mo - nm);
        mx = nm;
    }
    if (!lane) { warp_m[wid] = mx; warp_s[wid] = sm; }
    __syncthreads();
    if (tid == 0) {
        float m0 = warp_m[0], m1 = warp_m[1];
        float nm = fmaxf(m0, m1);
        float S = warp_s[0] * __expf(m0 - nm) + warp_s[1] * __expf(m1 - nm);
        smx = nm;
        sinv = 1.0f / (S + 1e-16f);
    }
    __syncthreads();
    float fmx = smx, finv = sinv;

    // phase 2: aggregate
    float acc = 0.f;
    for (int base = s0; base < s1; base += 64) {
        int cnt = min(64, s1 - base);
        if (tid < cnt) {
            int s = g_colsrc[base + tid];
            float ev = as_[s] + adv;
            ev = ev >= 0.f ? ev : NEG_SLOPE * ev;
            wsm[tid] = __expf(ev - fmx) * finv;
            ssm[tid] = s;
        }
        __syncthreads();
        #pragma unroll 4
        for (int e = 0; e < cnt; e++)
            acc += wsm[e] * __half2float(xwh[(size_t)ssm[e] * F2 + tid]);
        __syncthreads();
    }

    float o = acc + bias[tid];
    o = (o - bnm[tid]) * (bng[tid] * rsqrtf(bnv[tid] + BN_EPS)) + bnb[tid];
    o = fmaxf(o, 0.f);
    atomicAdd(&g_gsum[batch[d] * F2 + tid], o);
}

// ---------------- classifier head + log_softmax ----------------
__global__ void head_kernel(const float* __restrict__ Wc1, const float* __restrict__ bc1,
                            const float* __restrict__ Wc2, const float* __restrict__ bc2,
                            float* __restrict__ out) {
    __shared__ float repr[64];
    __shared__ float hc[64];
    __shared__ float logit[2];
    int g = blockIdx.x, j = threadIdx.x;
    float inv = 1.f / fmaxf(g_gcnt[g], 1.f);
    repr[j] = g_gsum[g * 64 + j] * inv;
    __syncthreads();
    float a = bc1[j];
    #pragma unroll
    for (int k = 0; k < 64; k++) a += repr[k] * Wc1[k * 64 + j];
    hc[j] = fmaxf(a, 0.f);
    __syncthreads();
    if (j < 2) {
        float l = bc2[j];
        for (int k = 0; k < 64; k++) l += hc[k] * Wc2[k * 2 + j];
        logit[j] = l;
    }
    __syncthreads();
    if (j == 0) {
        float l0 = logit[0], l1 = logit[1];
        float mx = fmaxf(l0, l1);
        float lse = mx + logf(expf(l0 - mx) + expf(l1 - mx));
        out[g * 2 + 0] = l0 - lse;
        out[g * 2 + 1] = l1 - lse;
    }
}

// ---------------- launch ----------------
extern "C" void kernel_launch(void* const* d_in, const int* in_sizes, int n_in,
                              void* d_out, int out_size) {
    const float* x        = (const float*)d_in[0];
    const int*   ei       = (const int*)  d_in[1];
    const int*   batch    = (const int*)  d_in[2];
    const float* W1       = (const float*)d_in[3];
    const float* att_src1 = (const float*)d_in[4];
    const float* att_dst1 = (const float*)d_in[5];
    const float* bias1    = (const float*)d_in[6];
    const float* bn1_g    = (const float*)d_in[7];
    const float* bn1_b    = (const float*)d_in[8];
    const float* bn1_m    = (const float*)d_in[9];
    const float* bn1_v    = (const float*)d_in[10];
    const float* W2       = (const float*)d_in[11];
    const float* att_src2 = (const float*)d_in[12];
    const float* att_dst2 = (const float*)d_in[13];
    const float* bias2    = (const float*)d_in[14];
    const float* bn2_g    = (const float*)d_in[15];
    const float* bn2_b    = (const float*)d_in[16];
    const float* bn2_m    = (const float*)d_in[17];
    const float* bn2_v    = (const float*)d_in[18];
    const float* Wc1      = (const float*)d_in[19];
    const float* bc1      = (const float*)d_in[20];
    const float* Wc2      = (const float*)d_in[21];
    const float* bc2      = (const float*)d_in[22];
    float* out = (float*)d_out;

    __half *p_xw1h, *p_xw2h;
    cudaGetSymbolAddress((void**)&p_xw1h, g_xw1h);
    cudaGetSymbolAddress((void**)&p_xw2h, g_xw2h);
    float *p_as1, *p_ad1, *p_as2, *p_ad2;
    cudaGetSymbolAddress((void**)&p_as1, g_as1);
    cudaGetSymbolAddress((void**)&p_ad1, g_ad1);
    cudaGetSymbolAddress((void**)&p_as2, g_as2);
    cudaGetSymbolAddress((void**)&p_ad2, g_ad2);

    // CSR build + init
    init_kernel<<<(NN + 255) / 256, 256>>>();
    count_kernel<<<(EE + 255) / 256, 256>>>(ei, batch);
    scan_kernel<<<1, 1024>>>();
    fill_kernel<<<(EP + 255) / 256, 256>>>(ei);

    const int MB = (NN + 127) / 128;   // 391

    // layer 1 GEMM (+ alpha1 epilogue)
    sgemm1_kernel<<<dim3(F1 / 64, MB), 256>>>(
        x, W1, p_xw1h, att_src1, att_dst1, p_as1, p_ad1);

    // layer 1 aggregation + BN/relu + fused layer-2 GEMV + alpha2
    agg1_kernel<<<NN, 256>>>(p_xw1h, p_as1, p_ad1,
                             bias1, bn1_g, bn1_b, bn1_m, bn1_v,
                             W2, att_src2, att_dst2,
                             p_xw2h, p_as2, p_ad2);

    // layer 2 aggregation + BN/relu + fused pooling
    agg2_kernel<<<NN, 64>>>(p_xw2h, p_as2, p_ad2,
                            bias2, bn2_g, bn2_b, bn2_m, bn2_v, batch);

    // classifier
    head_kernel<<<GG, 64>>>(Wc1, bc1, Wc2, bc2, out);
}

// round 7
// speedup vs baseline: 1.4127x; 1.4127x over previous
#include <cuda_runtime.h>
#include <cuda_fp16.h>
#include <math.h>
#include <stdint.h>

#define NN   50000
#define EE   1600000
#define EP   (EE + NN)
#define GG   64
#define DIN  128
#define HID  64
#define HH1  4
#define F1   (HH1 * HID)   // 256
#define F2   HID           // 64
#define NEG_SLOPE 0.2f
#define BN_EPS 1e-5f

// ---------------- device scratch ----------------
__device__ __half g_xh  [(size_t)NN * DIN];  // fp16 input features
__device__ __half g_W1h [DIN * F1];
__device__ __half g_W2h [F1 * F2];
__device__ __half g_xw1h[(size_t)NN * F1];   // fp16 gather table (layer 1)
__device__ __half g_h1h [(size_t)NN * F1];   // fp16 h1 (layer-2 GEMM input)
__device__ __half g_xw2h[(size_t)NN * F2];   // fp16 gather table (layer 2)
__device__ float  g_as1[NN * HH1], g_ad1[NN * HH1];
__device__ float  g_m1 [NN * HH1], g_sc1[NN * HH1];
__device__ float  g_as2[NN], g_ad2[NN];
__device__ float  g_m2 [NN], g_sc2[NN];
__device__ int    g_deg[NN];
__device__ int    g_rowptr[NN + 1];
__device__ int    g_cursor[NN];
__device__ int    g_colsrc[EP];
__device__ float  g_gsum[GG * F2];
__device__ float  g_gcnt[GG];

// ---------------- fp32 -> fp16 conversion ----------------
__global__ void f2h_kernel(const float* __restrict__ src, __half* __restrict__ dst, int n4) {
    int i = blockIdx.x * blockDim.x + threadIdx.x;
    if (i < n4) {
        float4 v = *(const float4*)&src[i * 4];
        *(__half2*)&dst[i * 4]     = __floats2half2_rn(v.x, v.y);
        *(__half2*)&dst[i * 4 + 2] = __floats2half2_rn(v.z, v.w);
    }
}

// ---------------- CSR build + init ----------------
__global__ void init_kernel() {
    int i = blockIdx.x * blockDim.x + threadIdx.x;
    if (i < NN) g_deg[i] = 1;                 // self loop
    if (i < GG * F2) g_gsum[i] = 0.f;
    if (i < GG) g_gcnt[i] = 0.f;
}

__global__ void count_kernel(const int* __restrict__ ei, const int* __restrict__ batch) {
    int i = blockIdx.x * blockDim.x + threadIdx.x;
    if (i < EE) atomicAdd(&g_deg[ei[EE + i]], 1);
    if (i < NN) atomicAdd(&g_gcnt[batch[i]], 1.0f);
}

__global__ void scan_kernel() {
    __shared__ int sums[1024];
    const int T = 1024;
    int tid = threadIdx.x;
    int chunk = (NN + T - 1) / T;
    int begin = tid * chunk;
    int end = min(begin + chunk, NN);
    int s = 0;
    for (int i = begin; i < end; i++) s += g_deg[i];
    sums[tid] = s;
    __syncthreads();
    for (int off = 1; off < T; off <<= 1) {
        int v = 0;
        if (tid >= off) v = sums[tid - off];
        __syncthreads();
        sums[tid] += v;
        __syncthreads();
    }
    int run = sums[tid] - s;
    for (int i = begin; i < end; i++) {
        g_rowptr[i] = run;
        g_cursor[i] = run;
        run += g_deg[i];
    }
    if (tid == T - 1) g_rowptr[NN] = EP;
}

__global__ void fill_kernel(const int* __restrict__ ei) {
    int i = blockIdx.x * blockDim.x + threadIdx.x;
    if (i >= EP) return;
    int s, d;
    if (i < EE) { s = ei[i]; d = ei[EE + i]; }
    else        { s = d = i - EE; }
    int pos = atomicAdd(&g_cursor[d], 1);
    g_colsrc[pos] = s;
}

// ---------------- HMMA GEMM: C = A[M,K]h @ B[K,N]h, fp32 accum -----------------
// 128x64 block tile, 8 warps each owning 16 rows x 64 cols (FULL head width,
// so the fused alpha dot is complete within one warp). K-chunk 32 in SMEM.
__device__ __forceinline__ void mma16816(float* c, uint32_t a0, uint32_t a1,
                                         uint32_t a2, uint32_t a3,
                                         uint32_t b0, uint32_t b1) {
    asm volatile(
        "mma.sync.aligned.m16n8k16.row.col.f32.f16.f16.f32 "
        "{%0,%1,%2,%3}, {%4,%5,%6,%7}, {%8,%9}, {%0,%1,%2,%3};\n"
        : "+f"(c[0]), "+f"(c[1]), "+f"(c[2]), "+f"(c[3])
        : "r"(a0), "r"(a1), "r"(a2), "r"(a3), "r"(b0), "r"(b1));
}

template<int HEADS>
__global__ __launch_bounds__(256) void hgemm_kernel(
        const __half* __restrict__ A, const __half* __restrict__ B,
        __half* __restrict__ Ch,
        const float* __restrict__ att_src, const float* __restrict__ att_dst,
        float* __restrict__ as_, float* __restrict__ ad_,
        int M, int Nn, int K) {
    __shared__ __half As[128][40];   // row-major, pad -> conflict-free frag loads
    __shared__ __half Bs[64][40];    // transposed: Bs[n][k]
    const int t    = threadIdx.x;
    const int lane = t & 31, wid = t >> 5;
    const int g  = lane >> 2, tg = lane & 3;
    const int rb = blockIdx.y * 128;
    const int cb = blockIdx.x * 64;
    const int head = blockIdx.x;

    float acc[8][4] = {};   // [n-tile of 8][c0..c3], warp tile 16x64

    for (int k0 = 0; k0 < K; k0 += 32) {
        // load A chunk 128x32
        #pragma unroll
        for (int r = 0; r < 2; r++) {
            int idx = t + r * 256;           // 0..511
            int row = idx >> 2, seg = idx & 3;
            int gr = rb + row;
            uint4 v = make_uint4(0u, 0u, 0u, 0u);
            if (gr < M) v = *(const uint4*)&A[(size_t)gr * K + k0 + seg * 8];
            *(uint4*)&As[row][seg * 8] = v;
        }
        // load B chunk 32x64, store transposed
        {
            int r = t >> 3, cseg = t & 7;
            uint4 v = *(const uint4*)&B[(size_t)(k0 + r) * Nn + cb + cseg * 8];
            const __half* hv = (const __half*)&v;
            #pragma unroll
            for (int j = 0; j < 8; j++) Bs[cseg * 8 + j][r] = hv[j];
        }
        __syncthreads();
        #pragma unroll
        for (int kk = 0; kk < 32; kk += 16) {
            int r0 = wid * 16 + g;
            uint32_t a0 = *(const uint32_t*)&As[r0    ][kk + tg * 2];
            uint32_t a1 = *(const uint32_t*)&As[r0 + 8][kk + tg * 2];
            uint32_t a2 = *(const uint32_t*)&As[r0    ][kk + tg * 2 + 8];
            uint32_t a3 = *(const uint32_t*)&As[r0 + 8][kk + tg * 2 + 8];
            #pragma unroll
            for (int nt = 0; nt < 8; nt++) {
                int c0 = nt * 8 + g;
                uint32_t b0 = *(const uint32_t*)&Bs[c0][kk + tg * 2];
                uint32_t b1 = *(const uint32_t*)&Bs[c0][kk + tg * 2 + 8];
                mma16816(acc[nt], a0, a1, a2, a3, b0, b1);
            }
        }
        __syncthreads();
    }

    // epilogue: fp16 store + complete alpha dot per row (warp owns all 64 cols)
    #pragma unroll
    for (int rv = 0; rv < 2; rv++) {
        int row = rb + wid * 16 + g + rv * 8;
        bool ok = row < M;
        float sp = 0.f, dp = 0.f;
        #pragma unroll
        for (int nt = 0; nt < 8; nt++) {
            int col = nt * 8 + tg * 2;   // local col in [0,64)
            float cx = acc[nt][rv * 2 + 0];
            float cy = acc[nt][rv * 2 + 1];
            if (ok)
                *(__half2*)&Ch[(size_t)row * Nn + cb + col] = __floats2half2_rn(cx, cy);
            sp += cx * att_src[head * 64 + col] + cy * att_src[head * 64 + col + 1];
            dp += cx * att_dst[head * 64 + col] + cy * att_dst[head * 64 + col + 1];
        }
        sp += __shfl_xor_sync(0xffffffffu, sp, 1);
        sp += __shfl_xor_sync(0xffffffffu, sp, 2);
        dp += __shfl_xor_sync(0xffffffffu, dp, 1);
        dp += __shfl_xor_sync(0xffffffffu, dp, 2);
        if (tg == 0 && ok) {
            as_[row * HEADS + head] = sp;
            ad_[row * HEADS + head] = dp;
        }
    }
}

// ---------------- one-pass online softmax stats: warp per dst node --------------
template<int HHEADS>
__global__ void stats_kernel(const float* __restrict__ as_, const float* __restrict__ ad_,
                             float* __restrict__ m_, float* __restrict__ sc_) {
    int w = (blockIdx.x * blockDim.x + threadIdx.x) >> 5;
    if (w >= NN) return;
    int lane = threadIdx.x & 31;
    int s0 = g_rowptr[w], s1 = g_rowptr[w + 1];
    float ad[HHEADS], mx[HHEADS], sum[HHEADS];
    #pragma unroll
    for (int h = 0; h < HHEADS; h++) {
        ad[h] = ad_[w * HHEADS + h]; mx[h] = -1e30f; sum[h] = 0.f;
    }
    for (int j = s0 + lane; j < s1; j += 32) {
        int s = g_colsrc[j];
        float av[HHEADS];
        if (HHEADS == 4) {
            float4 v = *(const float4*)&as_[(size_t)s * 4];
            av[0] = v.x; av[1 % HHEADS] = v.y; av[2 % HHEADS] = v.z; av[3 % HHEADS] = v.w;
        } else {
            #pragma unroll
            for (int h = 0; h < HHEADS; h++) av[h] = as_[s * HHEADS + h];
        }
        #pragma unroll
        for (int h = 0; h < HHEADS; h++) {
            float e = av[h] + ad[h];
            e = e >= 0.f ? e : NEG_SLOPE * e;
            float nm = fmaxf(mx[h], e);
            sum[h] = sum[h] * __expf(mx[h] - nm) + __expf(e - nm);
            mx[h] = nm;
        }
    }
    #pragma unroll
    for (int h = 0; h < HHEADS; h++) {
        #pragma unroll
        for (int off = 16; off; off >>= 1) {
            float mo = __shfl_xor_sync(0xffffffffu, mx[h], off);
            float so = __shfl_xor_sync(0xffffffffu, sum[h], off);
            float nm = fmaxf(mx[h], mo);
            sum[h] = sum[h] * __expf(mx[h] - nm) + so * __expf(mo - nm);
            mx[h] = nm;
        }
    }
    if (!lane) {
        #pragma unroll
        for (int h = 0; h < HHEADS; h++) {
            m_ [w * HHEADS + h] = mx[h];
            sc_[w * HHEADS + h] = 1.0f / (sum[h] + 1e-16f);
        }
    }
}

// ---------------- aggregation over fp16 gather table ---------------------------
template<int HHEADS, bool POOL>
__global__ void agg_kernel(const __half* __restrict__ xwh,
                           const float* __restrict__ as_, const float* __restrict__ ad_,
                           const float* __restrict__ m_, const float* __restrict__ sc_,
                           const float* __restrict__ bias,
                           const float* __restrict__ bng, const float* __restrict__ bnb,
                           const float* __restrict__ bnm, const float* __restrict__ bnv,
                           __half* __restrict__ hout, const int* __restrict__ batch) {
    constexpr int F = HHEADS * 64;
    const int d = blockIdx.x;
    const int tid = threadIdx.x;
    __shared__ float wsm[64 * HHEADS];
    __shared__ int   ssm[64];
    int s0 = g_rowptr[d], s1 = g_rowptr[d + 1];
    float acc = 0.f;
    for (int base = s0; base < s1; base += 64) {
        int cnt = min(64, s1 - base);
        if (tid < cnt * HHEADS) {
            int e = tid / HHEADS, h = tid % HHEADS;
            int s = g_colsrc[base + e];
            float ev = as_[s * HHEADS + h] + ad_[d * HHEADS + h];
            ev = ev >= 0.f ? ev : NEG_SLOPE * ev;
            wsm[e * HHEADS + h] = __expf(ev - m_[d * HHEADS + h]) * sc_[d * HHEADS + h];
            if (h == 0) ssm[e] = s;
        }
        __syncthreads();
        int h = tid >> 6;
        #pragma unroll 4
        for (int e = 0; e < cnt; e++)
            acc += wsm[e * HHEADS + h] * __half2float(xwh[(size_t)ssm[e] * F + tid]);
        __syncthreads();
    }
    float o = acc + bias[tid];
    o = (o - bnm[tid]) * (bng[tid] * rsqrtf(bnv[tid] + BN_EPS)) + bnb[tid];
    o = fmaxf(o, 0.f);
    if (POOL) {
        atomicAdd(&g_gsum[batch[d] * F2 + tid], o);
    } else {
        hout[(size_t)d * F + tid] = __float2half_rn(o);
    }
}

// ---------------- classifier head + log_softmax ----------------
__global__ void head_kernel(const float* __restrict__ Wc1, const float* __restrict__ bc1,
                            const float* __restrict__ Wc2, const float* __restrict__ bc2,
                            float* __restrict__ out) {
    __shared__ float repr[64];
    __shared__ float hc[64];
    __shared__ float logit[2];
    int g = blockIdx.x, j = threadIdx.x;
    float inv = 1.f / fmaxf(g_gcnt[g], 1.f);
    repr[j] = g_gsum[g * 64 + j] * inv;
    __syncthreads();
    float a = bc1[j];
    #pragma unroll
    for (int k = 0; k < 64; k++) a += repr[k] * Wc1[k * 64 + j];
    hc[j] = fmaxf(a, 0.f);
    __syncthreads();
    if (j < 2) {
        float l = bc2[j];
        for (int k = 0; k < 64; k++) l += hc[k] * Wc2[k * 2 + j];
        logit[j] = l;
    }
    __syncthreads();
    if (j == 0) {
        float l0 = logit[0], l1 = logit[1];
        float mx = fmaxf(l0, l1);
        float lse = mx + logf(expf(l0 - mx) + expf(l1 - mx));
        out[g * 2 + 0] = l0 - lse;
        out[g * 2 + 1] = l1 - lse;
    }
}

// ---------------- launch ----------------
extern "C" void kernel_launch(void* const* d_in, const int* in_sizes, int n_in,
                              void* d_out, int out_size) {
    const float* x        = (const float*)d_in[0];
    const int*   ei       = (const int*)  d_in[1];
    const int*   batch    = (const int*)  d_in[2];
    const float* W1       = (const float*)d_in[3];
    const float* att_src1 = (const float*)d_in[4];
    const float* att_dst1 = (const float*)d_in[5];
    const float* bias1    = (const float*)d_in[6];
    const float* bn1_g    = (const float*)d_in[7];
    const float* bn1_b    = (const float*)d_in[8];
    const float* bn1_m    = (const float*)d_in[9];
    const float* bn1_v    = (const float*)d_in[10];
    const float* W2       = (const float*)d_in[11];
    const float* att_src2 = (const float*)d_in[12];
    const float* att_dst2 = (const float*)d_in[13];
    const float* bias2    = (const float*)d_in[14];
    const float* bn2_g    = (const float*)d_in[15];
    const float* bn2_b    = (const float*)d_in[16];
    const float* bn2_m    = (const float*)d_in[17];
    const float* bn2_v    = (const float*)d_in[18];
    const float* Wc1      = (const float*)d_in[19];
    const float* bc1      = (const float*)d_in[20];
    const float* Wc2      = (const float*)d_in[21];
    const float* bc2      = (const float*)d_in[22];
    float* out = (float*)d_out;

    __half *p_xh, *p_W1h, *p_W2h, *p_xw1h, *p_h1h, *p_xw2h;
    cudaGetSymbolAddress((void**)&p_xh,   g_xh);
    cudaGetSymbolAddress((void**)&p_W1h,  g_W1h);
    cudaGetSymbolAddress((void**)&p_W2h,  g_W2h);
    cudaGetSymbolAddress((void**)&p_xw1h, g_xw1h);
    cudaGetSymbolAddress((void**)&p_h1h,  g_h1h);
    cudaGetSymbolAddress((void**)&p_xw2h, g_xw2h);
    float *p_as1, *p_ad1, *p_m1, *p_sc1, *p_as2, *p_ad2, *p_m2, *p_sc2;
    cudaGetSymbolAddress((void**)&p_as1, g_as1);
    cudaGetSymbolAddress((void**)&p_ad1, g_ad1);
    cudaGetSymbolAddress((void**)&p_m1,  g_m1);
    cudaGetSymbolAddress((void**)&p_sc1, g_sc1);
    cudaGetSymbolAddress((void**)&p_as2, g_as2);
    cudaGetSymbolAddress((void**)&p_ad2, g_ad2);
    cudaGetSymbolAddress((void**)&p_m2,  g_m2);
    cudaGetSymbolAddress((void**)&p_sc2, g_sc2);

    // CSR build + init
    init_kernel<<<(NN + 255) / 256, 256>>>();
    count_kernel<<<(EE + 255) / 256, 256>>>(ei, batch);
    scan_kernel<<<1, 1024>>>();
    fill_kernel<<<(EP + 255) / 256, 256>>>(ei);

    // fp16 conversions
    f2h_kernel<<<(NN * DIN / 4 + 255) / 256, 256>>>(x,  p_xh,  NN * DIN / 4);
    f2h_kernel<<<(DIN * F1 / 4 + 255) / 256, 256>>>(W1, p_W1h, DIN * F1 / 4);
    f2h_kernel<<<(F1 * F2 / 4 + 255) / 256, 256>>>(W2,  p_W2h, F1 * F2 / 4);

    const int MB = (NN + 127) / 128;   // 391

    // ---- layer 1 ----
    hgemm_kernel<HH1><<<dim3(F1 / 64, MB), 256>>>(
        p_xh, p_W1h, p_xw1h, att_src1, att_dst1, p_as1, p_ad1, NN, F1, DIN);
    stats_kernel<HH1><<<(NN * 32 + 255) / 256, 256>>>(p_as1, p_ad1, p_m1, p_sc1);
    agg_kernel<HH1, false><<<NN, 256>>>(p_xw1h, p_as1, p_ad1, p_m1, p_sc1,
                                        bias1, bn1_g, bn1_b, bn1_m, bn1_v, p_h1h, nullptr);

    // ---- layer 2 ----
    hgemm_kernel<1><<<dim3(F2 / 64, MB), 256>>>(
        p_h1h, p_W2h, p_xw2h, att_src2, att_dst2, p_as2, p_ad2, NN, F2, F1);
    stats_kernel<1><<<(NN * 32 + 255) / 256, 256>>>(p_as2, p_ad2, p_m2, p_sc2);
    agg_kernel<1, true><<<NN, 64>>>(p_xw2h, p_as2, p_ad2, p_m2, p_sc2,
                                    bias2, bn2_g, bn2_b, bn2_m, bn2_v, nullptr, batch);

    // ---- classifier ----
    head_kernel<<<GG, 64>>>(Wc1, bc1, Wc2, bc2, out);
}

// round 9
// speedup vs baseline: 1.5829x; 1.1205x over previous
#include <cuda_runtime.h>
#include <cuda_fp16.h>
#include <math.h>
#include <stdint.h>

#define NN   50000
#define EE   1600000
#define EP   (EE + NN)
#define GG   64
#define DIN  128
#define HID  64
#define HH1  4
#define F1   (HH1 * HID)   // 256
#define F2   HID           // 64
#define NEG_SLOPE 0.2f
#define BN_EPS 1e-5f

// ---------------- device scratch ----------------
__device__ __half g_xh  [(size_t)NN * DIN];
__device__ __half g_W1h [DIN * F1];
__device__ __half g_W2h [F1 * F2];
__device__ __half g_xw1h[(size_t)NN * F1];   // fp16 gather table (layer 1)
__device__ __half g_h1h [(size_t)NN * F1];   // fp16 h1 (layer-2 GEMM input)
__device__ __half g_xw2h[(size_t)NN * F2];   // fp16 gather table (layer 2)
__device__ float  g_as1[NN * HH1], g_ad1[NN * HH1];
__device__ float  g_as2[NN], g_ad2[NN];
__device__ float  g_w1[(size_t)EP * HH1];    // per-edge softmax weights, layer 1
__device__ float  g_w2[EP];                  // layer 2
__device__ int    g_deg[NN];
__device__ int    g_rowptr[NN + 1];
__device__ int    g_cursor[NN];
__device__ int    g_colsrc[EP];
__device__ float  g_gsum[GG * F2];
__device__ float  g_gcnt[GG];

// ---------------- fp32 -> fp16 conversion ----------------
__global__ void f2h_kernel(const float* __restrict__ src, __half* __restrict__ dst, int n4) {
    int i = blockIdx.x * blockDim.x + threadIdx.x;
    if (i < n4) {
        float4 v = *(const float4*)&src[i * 4];
        *(__half2*)&dst[i * 4]     = __floats2half2_rn(v.x, v.y);
        *(__half2*)&dst[i * 4 + 2] = __floats2half2_rn(v.z, v.w);
    }
}

// ---------------- CSR build + init ----------------
__global__ void init_kernel() {
    int i = blockIdx.x * blockDim.x + threadIdx.x;
    if (i < NN) g_deg[i] = 1;                 // self loop
    if (i < GG * F2) g_gsum[i] = 0.f;
    if (i < GG) g_gcnt[i] = 0.f;
}

__global__ void count_kernel(const int* __restrict__ ei, const int* __restrict__ batch) {
    int i = blockIdx.x * blockDim.x + threadIdx.x;
    if (i < EE) atomicAdd(&g_deg[ei[EE + i]], 1);
    if (i < NN) atomicAdd(&g_gcnt[batch[i]], 1.0f);
}

__global__ void scan_kernel() {
    __shared__ int sums[1024];
    const int T = 1024;
    int tid = threadIdx.x;
    int chunk = (NN + T - 1) / T;
    int begin = tid * chunk;
    int end = min(begin + chunk, NN);
    int s = 0;
    for (int i = begin; i < end; i++) s += g_deg[i];
    sums[tid] = s;
    __syncthreads();
    for (int off = 1; off < T; off <<= 1) {
        int v = 0;
        if (tid >= off) v = sums[tid - off];
        __syncthreads();
        sums[tid] += v;
        __syncthreads();
    }
    int run = sums[tid] - s;
    for (int i = begin; i < end; i++) {
        g_rowptr[i] = run;
        g_cursor[i] = run;
        run += g_deg[i];
    }
    if (tid == T - 1) g_rowptr[NN] = EP;
}

__global__ void fill_kernel(const int* __restrict__ ei) {
    int i = blockIdx.x * blockDim.x + threadIdx.x;
    if (i >= EP) return;
    int s, d;
    if (i < EE) { s = ei[i]; d = ei[EE + i]; }
    else        { s = d = i - EE; }
    int pos = atomicAdd(&g_cursor[d], 1);
    g_colsrc[pos] = s;
}

// ---------------- HMMA GEMM (unchanged from R7) -----------------
__device__ __forceinline__ void mma16816(float* c, uint32_t a0, uint32_t a1,
                                         uint32_t a2, uint32_t a3,
                                         uint32_t b0, uint32_t b1) {
    asm volatile(
        "mma.sync.aligned.m16n8k16.row.col.f32.f16.f16.f32 "
        "{%0,%1,%2,%3}, {%4,%5,%6,%7}, {%8,%9}, {%0,%1,%2,%3};\n"
        : "+f"(c[0]), "+f"(c[1]), "+f"(c[2]), "+f"(c[3])
        : "r"(a0), "r"(a1), "r"(a2), "r"(a3), "r"(b0), "r"(b1));
}

template<int HEADS>
__global__ __launch_bounds__(256) void hgemm_kernel(
        const __half* __restrict__ A, const __half* __restrict__ B,
        __half* __restrict__ Ch,
        const float* __restrict__ att_src, const float* __restrict__ att_dst,
        float* __restrict__ as_, float* __restrict__ ad_,
        int M, int Nn, int K) {
    __shared__ __half As[128][40];
    __shared__ __half Bs[64][40];
    const int t    = threadIdx.x;
    const int lane = t & 31, wid = t >> 5;
    const int g  = lane >> 2, tg = lane & 3;
    const int rb = blockIdx.y * 128;
    const int cb = blockIdx.x * 64;
    const int head = blockIdx.x;

    float acc[8][4] = {};

    for (int k0 = 0; k0 < K; k0 += 32) {
        #pragma unroll
        for (int r = 0; r < 2; r++) {
            int idx = t + r * 256;
            int row = idx >> 2, seg = idx & 3;
            int gr = rb + row;
            uint4 v = make_uint4(0u, 0u, 0u, 0u);
            if (gr < M) v = *(const uint4*)&A[(size_t)gr * K + k0 + seg * 8];
            *(uint4*)&As[row][seg * 8] = v;
        }
        {
            int r = t >> 3, cseg = t & 7;
            uint4 v = *(const uint4*)&B[(size_t)(k0 + r) * Nn + cb + cseg * 8];
            const __half* hv = (const __half*)&v;
            #pragma unroll
            for (int j = 0; j < 8; j++) Bs[cseg * 8 + j][r] = hv[j];
        }
        __syncthreads();
        #pragma unroll
        for (int kk = 0; kk < 32; kk += 16) {
            int r0 = wid * 16 + g;
            uint32_t a0 = *(const uint32_t*)&As[r0    ][kk + tg * 2];
            uint32_t a1 = *(const uint32_t*)&As[r0 + 8][kk + tg * 2];
            uint32_t a2 = *(const uint32_t*)&As[r0    ][kk + tg * 2 + 8];
            uint32_t a3 = *(const uint32_t*)&As[r0 + 8][kk + tg * 2 + 8];
            #pragma unroll
            for (int nt = 0; nt < 8; nt++) {
                int c0 = nt * 8 + g;
                uint32_t b0 = *(const uint32_t*)&Bs[c0][kk + tg * 2];
                uint32_t b1 = *(const uint32_t*)&Bs[c0][kk + tg * 2 + 8];
                mma16816(acc[nt], a0, a1, a2, a3, b0, b1);
            }
        }
        __syncthreads();
    }

    #pragma unroll
    for (int rv = 0; rv < 2; rv++) {
        int row = rb + wid * 16 + g + rv * 8;
        bool ok = row < M;
        float sp = 0.f, dp = 0.f;
        #pragma unroll
        for (int nt = 0; nt < 8; nt++) {
            int col = nt * 8 + tg * 2;
            float cx = acc[nt][rv * 2 + 0];
            float cy = acc[nt][rv * 2 + 1];
            if (ok)
                *(__half2*)&Ch[(size_t)row * Nn + cb + col] = __floats2half2_rn(cx, cy);
            sp += cx * att_src[head * 64 + col] + cy * att_src[head * 64 + col + 1];
            dp += cx * att_dst[head * 64 + col] + cy * att_dst[head * 64 + col + 1];
        }
        sp += __shfl_xor_sync(0xffffffffu, sp, 1);
        sp += __shfl_xor_sync(0xffffffffu, sp, 2);
        dp += __shfl_xor_sync(0xffffffffu, dp, 1);
        dp += __shfl_xor_sync(0xffffffffu, dp, 2);
        if (tg == 0 && ok) {
            as_[row * HEADS + head] = sp;
            ad_[row * HEADS + head] = dp;
        }
    }
}

// ---------------- stats + per-edge weight materialization ----------------------
// warp per dst: pass 1 = online max/sum; pass 2 = write w[j] (fp32, coalesced).
template<int HHEADS>
__global__ void stats_kernel(const float* __restrict__ as_, const float* __restrict__ ad_,
                             float* __restrict__ wout) {
    int w = (blockIdx.x * blockDim.x + threadIdx.x) >> 5;
    if (w >= NN) return;
    int lane = threadIdx.x & 31;
    int s0 = g_rowptr[w], s1 = g_rowptr[w + 1];
    float ad[HHEADS], mx[HHEADS], sum[HHEADS];
    #pragma unroll
    for (int h = 0; h < HHEADS; h++) {
        ad[h] = ad_[w * HHEADS + h]; mx[h] = -1e30f; sum[h] = 0.f;
    }
    for (int j = s0 + lane; j < s1; j += 32) {
        int s = g_colsrc[j];
        float av[HHEADS];
        if (HHEADS == 4) {
            float4 v = *(const float4*)&as_[(size_t)s * 4];
            av[0] = v.x; av[1 % HHEADS] = v.y; av[2 % HHEADS] = v.z; av[3 % HHEADS] = v.w;
        } else {
            #pragma unroll
            for (int h = 0; h < HHEADS; h++) av[h] = as_[s * HHEADS + h];
        }
        #pragma unroll
        for (int h = 0; h < HHEADS; h++) {
            float e = av[h] + ad[h];
            e = e >= 0.f ? e : NEG_SLOPE * e;
            float nm = fmaxf(mx[h], e);
            sum[h] = sum[h] * __expf(mx[h] - nm) + __expf(e - nm);
            mx[h] = nm;
        }
    }
    #pragma unroll
    for (int h = 0; h < HHEADS; h++) {
        #pragma unroll
        for (int off = 16; off; off >>= 1) {
            float mo = __shfl_xor_sync(0xffffffffu, mx[h], off);
            float so = __shfl_xor_sync(0xffffffffu, sum[h], off);
            float nm = fmaxf(mx[h], mo);
            sum[h] = sum[h] * __expf(mx[h] - nm) + so * __expf(mo - nm);
            mx[h] = nm;
        }
    }
    float inv[HHEADS];
    #pragma unroll
    for (int h = 0; h < HHEADS; h++) inv[h] = 1.0f / (sum[h] + 1e-16f);

    // pass 2: materialize normalized weights (coalesced stores)
    for (int j = s0 + lane; j < s1; j += 32) {
        int s = g_colsrc[j];
        if (HHEADS == 4) {
            float4 v = *(const float4*)&as_[(size_t)s * 4];
            float av[4] = {v.x, v.y, v.z, v.w};
            float wv[4];
            #pragma unroll
            for (int h = 0; h < 4; h++) {
                float e = av[h] + ad[h];
                e = e >= 0.f ? e : NEG_SLOPE * e;
                wv[h] = __expf(e - mx[h]) * inv[h];
            }
            *(float4*)&wout[(size_t)j * 4] = make_float4(wv[0], wv[1], wv[2], wv[3]);
        } else {
            float e = as_[s] + ad[0];
            e = e >= 0.f ? e : NEG_SLOPE * e;
            wout[j] = __expf(e - mx[0]) * inv[0];
        }
    }
}

// ---------------- agg1: warp per (dst, 64-col group), sync-free ----------------
__global__ __launch_bounds__(256) void agg1_kernel(
        const __half* __restrict__ xwh, const float* __restrict__ wtab,
        const float* __restrict__ bias,
        const float* __restrict__ bng, const float* __restrict__ bnb,
        const float* __restrict__ bnm, const float* __restrict__ bnv,
        __half* __restrict__ hout) {
    int gw = (blockIdx.x * 256 + threadIdx.x) >> 5;
    int d = gw >> 2, q = gw & 3;
    if (d >= NN) return;
    int lane = threadIdx.x & 31;
    int s0 = g_rowptr[d], s1 = g_rowptr[d + 1];
    const __half* bp = xwh + q * 64 + lane * 2;
    float ax = 0.f, ay = 0.f;
    int j = s0;
    for (; j + 4 <= s1; j += 4) {
        int sa = g_colsrc[j], sb = g_colsrc[j + 1], sc = g_colsrc[j + 2], sd = g_colsrc[j + 3];
        float wa = wtab[(size_t)j * 4 + q];
        float wb = wtab[(size_t)(j + 1) * 4 + q];
        float wc = wtab[(size_t)(j + 2) * 4 + q];
        float wd = wtab[(size_t)(j + 3) * 4 + q];
        float2 va = __half22float2(*(const __half2*)(bp + (size_t)sa * F1));
        float2 vb = __half22float2(*(const __half2*)(bp + (size_t)sb * F1));
        float2 vc = __half22float2(*(const __half2*)(bp + (size_t)sc * F1));
        float2 vd = __half22float2(*(const __half2*)(bp + (size_t)sd * F1));
        ax += wa * va.x + wb * vb.x + wc * vc.x + wd * vd.x;
        ay += wa * va.y + wb * vb.y + wc * vc.y + wd * vd.y;
    }
    for (; j < s1; j++) {
        int s = g_colsrc[j];
        float w = wtab[(size_t)j * 4 + q];
        float2 v = __half22float2(*(const __half2*)(bp + (size_t)s * F1));
        ax += w * v.x;
        ay += w * v.y;
    }
    int col = q * 64 + lane * 2;
    float2 bi = *(const float2*)&bias[col];
    float2 bm = *(const float2*)&bnm[col];
    float2 bg = *(const float2*)&bng[col];
    float2 bv = *(const float2*)&bnv[col];
    float2 bb = *(const float2*)&bnb[col];
    float o0 = (ax + bi.x - bm.x) * (bg.x * rsqrtf(bv.x + BN_EPS)) + bb.x;
    float o1 = (ay + bi.y - bm.y) * (bg.y * rsqrtf(bv.y + BN_EPS)) + bb.y;
    o0 = fmaxf(o0, 0.f);
    o1 = fmaxf(o1, 0.f);
    *(__half2*)&hout[(size_t)d * F1 + col] = __floats2half2_rn(o0, o1);
}

// ---------------- agg2: warp per dst + fused pooling ---------------------------
__global__ __launch_bounds__(256) void agg2_kernel(
        const __half* __restrict__ xwh, const float* __restrict__ wtab,
        const float* __restrict__ bias,
        const float* __restrict__ bng, const float* __restrict__ bnb,
        const float* __restrict__ bnm, const float* __restrict__ bnv,
        const int* __restrict__ batch) {
    int d = (blockIdx.x * 256 + threadIdx.x) >> 5;
    if (d >= NN) return;
    int lane = threadIdx.x & 31;
    int s0 = g_rowptr[d], s1 = g_rowptr[d + 1];
    const __half* bp = xwh + lane * 2;
    float ax = 0.f, ay = 0.f;
    int j = s0;
    for (; j + 4 <= s1; j += 4) {
        int sa = g_colsrc[j], sb = g_colsrc[j + 1], sc = g_colsrc[j + 2], sd = g_colsrc[j + 3];
        float wa = wtab[j], wb = wtab[j + 1], wc = wtab[j + 2], wd = wtab[j + 3];
        float2 va = __half22float2(*(const __half2*)(bp + (size_t)sa * F2));
        float2 vb = __half22float2(*(const __half2*)(bp + (size_t)sb * F2));
        float2 vc = __half22float2(*(const __half2*)(bp + (size_t)sc * F2));
        float2 vd = __half22float2(*(const __half2*)(bp + (size_t)sd * F2));
        ax += wa * va.x + wb * vb.x + wc * vc.x + wd * vd.x;
        ay += wa * va.y + wb * vb.y + wc * vc.y + wd * vd.y;
    }
    for (; j < s1; j++) {
        int s = g_colsrc[j];
        float w = wtab[j];
        float2 v = __half22float2(*(const __half2*)(bp + (size_t)s * F2));
        ax += w * v.x;
        ay += w * v.y;
    }
    int col = lane * 2;
    float2 bi = *(const float2*)&bias[col];
    float2 bm = *(const float2*)&bnm[col];
    float2 bg = *(const float2*)&bng[col];
    float2 bv = *(const float2*)&bnv[col];
    float2 bb = *(const float2*)&bnb[col];
    float o0 = (ax + bi.x - bm.x) * (bg.x * rsqrtf(bv.x + BN_EPS)) + bb.x;
    float o1 = (ay + bi.y - bm.y) * (bg.y * rsqrtf(bv.y + BN_EPS)) + bb.y;
    o0 = fmaxf(o0, 0.f);
    o1 = fmaxf(o1, 0.f);
    int g = batch[d];
    atomicAdd(&g_gsum[g * F2 + col],     o0);
    atomicAdd(&g_gsum[g * F2 + col + 1], o1);
}

// ---------------- classifier head + log_softmax ----------------
__global__ void head_kernel(const float* __restrict__ Wc1, const float* __restrict__ bc1,
                            const float* __restrict__ Wc2, const float* __restrict__ bc2,
                            float* __restrict__ out) {
    __shared__ float repr[64];
    __shared__ float hc[64];
    __shared__ float logit[2];
    int g = blockIdx.x, j = threadIdx.x;
    float inv = 1.f / fmaxf(g_gcnt[g], 1.f);
    repr[j] = g_gsum[g * 64 + j] * inv;
    __syncthreads();
    float a = bc1[j];
    #pragma unroll
    for (int k = 0; k < 64; k++) a += repr[k] * Wc1[k * 64 + j];
    hc[j] = fmaxf(a, 0.f);
    __syncthreads();
    if (j < 2) {
        float l = bc2[j];
        for (int k = 0; k < 64; k++) l += hc[k] * Wc2[k * 2 + j];
        logit[j] = l;
    }
    __syncthreads();
    if (j == 0) {
        float l0 = logit[0], l1 = logit[1];
        float mx = fmaxf(l0, l1);
        float lse = mx + logf(expf(l0 - mx) + expf(l1 - mx));
        out[g * 2 + 0] = l0 - lse;
        out[g * 2 + 1] = l1 - lse;
    }
}

// ---------------- launch ----------------
extern "C" void kernel_launch(void* const* d_in, const int* in_sizes, int n_in,
                              void* d_out, int out_size) {
    const float* x        = (const float*)d_in[0];
    const int*   ei       = (const int*)  d_in[1];
    const int*   batch    = (const int*)  d_in[2];
    const float* W1       = (const float*)d_in[3];
    const float* att_src1 = (const float*)d_in[4];
    const float* att_dst1 = (const float*)d_in[5];
    const float* bias1    = (const float*)d_in[6];
    const float* bn1_g    = (const float*)d_in[7];
    const float* bn1_b    = (const float*)d_in[8];
    const float* bn1_m    = (const float*)d_in[9];
    const float* bn1_v    = (const float*)d_in[10];
    const float* W2       = (const float*)d_in[11];
    const float* att_src2 = (const float*)d_in[12];
    const float* att_dst2 = (const float*)d_in[13];
    const float* bias2    = (const float*)d_in[14];
    const float* bn2_g    = (const float*)d_in[15];
    const float* bn2_b    = (const float*)d_in[16];
    const float* bn2_m    = (const float*)d_in[17];
    const float* bn2_v    = (const float*)d_in[18];
    const float* Wc1      = (const float*)d_in[19];
    const float* bc1      = (const float*)d_in[20];
    const float* Wc2      = (const float*)d_in[21];
    const float* bc2      = (const float*)d_in[22];
    float* out = (float*)d_out;

    __half *p_xh, *p_W1h, *p_W2h, *p_xw1h, *p_h1h, *p_xw2h;
    cudaGetSymbolAddress((void**)&p_xh,   g_xh);
    cudaGetSymbolAddress((void**)&p_W1h,  g_W1h);
    cudaGetSymbolAddress((void**)&p_W2h,  g_W2h);
    cudaGetSymbolAddress((void**)&p_xw1h, g_xw1h);
    cudaGetSymbolAddress((void**)&p_h1h,  g_h1h);
    cudaGetSymbolAddress((void**)&p_xw2h, g_xw2h);
    float *p_as1, *p_ad1, *p_as2, *p_ad2, *p_w1, *p_w2;
    cudaGetSymbolAddress((void**)&p_as1, g_as1);
    cudaGetSymbolAddress((void**)&p_ad1, g_ad1);
    cudaGetSymbolAddress((void**)&p_as2, g_as2);
    cudaGetSymbolAddress((void**)&p_ad2, g_ad2);
    cudaGetSymbolAddress((void**)&p_w1,  g_w1);
    cudaGetSymbolAddress((void**)&p_w2,  g_w2);

    // CSR build + init
    init_kernel<<<(NN + 255) / 256, 256>>>();
    count_kernel<<<(EE + 255) / 256, 256>>>(ei, batch);
    scan_kernel<<<1, 1024>>>();
    fill_kernel<<<(EP + 255) / 256, 256>>>(ei);

    // fp16 conversions
    f2h_kernel<<<(NN * DIN / 4 + 255) / 256, 256>>>(x,  p_xh,  NN * DIN / 4);
    f2h_kernel<<<(DIN * F1 / 4 + 255) / 256, 256>>>(W1, p_W1h, DIN * F1 / 4);
    f2h_kernel<<<(F1 * F2 / 4 + 255) / 256, 256>>>(W2,  p_W2h, F1 * F2 / 4);

    const int MB = (NN + 127) / 128;   // 391

    // ---- layer 1 ----
    hgemm_kernel<HH1><<<dim3(F1 / 64, MB), 256>>>(
        p_xh, p_W1h, p_xw1h, att_src1, att_dst1, p_as1, p_ad1, NN, F1, DIN);
    stats_kernel<HH1><<<(NN * 32 + 255) / 256, 256>>>(p_as1, p_ad1, p_w1);
    agg1_kernel<<<(NN * HH1 * 32 + 255) / 256, 256>>>(
        p_xw1h, p_w1, bias1, bn1_g, bn1_b, bn1_m, bn1_v, p_h1h);

    // ---- layer 2 ----
    hgemm_kernel<1><<<dim3(F2 / 64, MB), 256>>>(
        p_h1h, p_W2h, p_xw2h, att_src2, att_dst2, p_as2, p_ad2, NN, F2, F1);
    stats_kernel<1><<<(NN * 32 + 255) / 256, 256>>>(p_as2, p_ad2, p_w2);
    agg2_kernel<<<(NN * 32 + 255) / 256, 256>>>(
        p_xw2h, p_w2, bias2, bn2_g, bn2_b, bn2_m, bn2_v, batch);

    // ---- classifier ----
    head_kernel<<<GG, 64>>>(Wc1, bc1, Wc2, bc2, out);
}

// round 10
// speedup vs baseline: 1.8638x; 1.1775x over previous
#include <cuda_runtime.h>
#include <cuda_fp16.h>
#include <math.h>
#include <stdint.h>

#define NN   50000
#define EE   1600000
#define EP   (EE + NN)
#define GG   64
#define DIN  128
#define HID  64
#define HH1  4
#define F1   (HH1 * HID)   // 256
#define F2   HID           // 64
#define NEG_SLOPE 0.2f
#define BN_EPS 1e-5f

// ---------------- device scratch ----------------
__device__ __half g_W1h [DIN * F1];
__device__ __half g_W2h [F1 * F2];
__device__ __half g_xw1h[(size_t)NN * F1];   // fp16 gather table (layer 1)
__device__ __half g_h1h [(size_t)NN * F1];   // fp16 h1 (layer-2 GEMM input)
__device__ __half g_xw2h[(size_t)NN * F2];   // fp16 gather table (layer 2)
__device__ float  g_as1[NN * HH1], g_ad1[NN * HH1];
__device__ float  g_as2[NN], g_ad2[NN];
__device__ float  g_w1[(size_t)EP * HH1];    // per-edge UNNORMALIZED exp weights, layer 1
__device__ float  g_w2[EP];                  // layer 2
__device__ float  g_inv1[NN * HH1];          // per-(dst,head) 1/sum
__device__ float  g_inv2[NN];
__device__ int    g_deg[NN];
__device__ int    g_rowptr[NN + 1];
__device__ int    g_cursor[NN];
__device__ int    g_colsrc[EP];
__device__ float  g_gsum[GG * F2];
__device__ float  g_gcnt[GG];

// ---------------- fp32 -> fp16 conversion (weights only) ----------------
__global__ void f2h_kernel(const float* __restrict__ src, __half* __restrict__ dst, int n4) {
    int i = blockIdx.x * blockDim.x + threadIdx.x;
    if (i < n4) {
        float4 v = *(const float4*)&src[i * 4];
        *(__half2*)&dst[i * 4]     = __floats2half2_rn(v.x, v.y);
        *(__half2*)&dst[i * 4 + 2] = __floats2half2_rn(v.z, v.w);
    }
}

// ---------------- CSR build + init ----------------
__global__ void init_kernel() {
    int i = blockIdx.x * blockDim.x + threadIdx.x;
    if (i < NN) g_deg[i] = 1;                 // self loop
    if (i < GG * F2) g_gsum[i] = 0.f;
    if (i < GG) g_gcnt[i] = 0.f;
}

__global__ void count_kernel(const int* __restrict__ ei, const int* __restrict__ batch) {
    int i = blockIdx.x * blockDim.x + threadIdx.x;
    if (i < EE) atomicAdd(&g_deg[ei[EE + i]], 1);
    if (i < NN) atomicAdd(&g_gcnt[batch[i]], 1.0f);
}

__global__ void scan_kernel() {
    __shared__ int sums[1024];
    const int T = 1024;
    int tid = threadIdx.x;
    int chunk = (NN + T - 1) / T;
    int begin = tid * chunk;
    int end = min(begin + chunk, NN);
    int s = 0;
    for (int i = begin; i < end; i++) s += g_deg[i];
    sums[tid] = s;
    __syncthreads();
    for (int off = 1; off < T; off <<= 1) {
        int v = 0;
        if (tid >= off) v = sums[tid - off];
        __syncthreads();
        sums[tid] += v;
        __syncthreads();
    }
    int run = sums[tid] - s;
    for (int i = begin; i < end; i++) {
        g_rowptr[i] = run;
        g_cursor[i] = run;
        run += g_deg[i];
    }
    if (tid == T - 1) g_rowptr[NN] = EP;
}

__global__ void fill_kernel(const int* __restrict__ ei) {
    int i = blockIdx.x * blockDim.x + threadIdx.x;
    if (i >= EP) return;
    int s, d;
    if (i < EE) { s = ei[i]; d = ei[EE + i]; }
    else        { s = d = i - EE; }
    int pos = atomicAdd(&g_cursor[d], 1);
    g_colsrc[pos] = s;
}

// ---------------- HMMA GEMM, optional fp32 A with inline convert ----------------
__device__ __forceinline__ void mma16816(float* c, uint32_t a0, uint32_t a1,
                                         uint32_t a2, uint32_t a3,
                                         uint32_t b0, uint32_t b1) {
    asm volatile(
        "mma.sync.aligned.m16n8k16.row.col.f32.f16.f16.f32 "
        "{%0,%1,%2,%3}, {%4,%5,%6,%7}, {%8,%9}, {%0,%1,%2,%3};\n"
        : "+f"(c[0]), "+f"(c[1]), "+f"(c[2]), "+f"(c[3])
        : "r"(a0), "r"(a1), "r"(a2), "r"(a3), "r"(b0), "r"(b1));
}

template<int HEADS, bool AF32>
__global__ __launch_bounds__(256) void hgemm_kernel(
        const void* __restrict__ Av, const __half* __restrict__ B,
        __half* __restrict__ Ch,
        const float* __restrict__ att_src, const float* __restrict__ att_dst,
        float* __restrict__ as_, float* __restrict__ ad_,
        int M, int Nn, int K) {
    __shared__ __half As[128][40];
    __shared__ __half Bs[64][40];
    const int t    = threadIdx.x;
    const int lane = t & 31, wid = t >> 5;
    const int g  = lane >> 2, tg = lane & 3;
    const int rb = blockIdx.y * 128;
    const int cb = blockIdx.x * 64;
    const int head = blockIdx.x;

    const __half* Ah = (const __half*)Av;
    const float*  Af = (const float*)Av;

    float acc[8][4] = {};

    for (int k0 = 0; k0 < K; k0 += 32) {
        #pragma unroll
        for (int r = 0; r < 2; r++) {
            int idx = t + r * 256;
            int row = idx >> 2, seg = idx & 3;
            int gr = rb + row;
            if (AF32) {
                __half tmp[8];
                if (gr < M) {
                    float4 v0 = *(const float4*)&Af[(size_t)gr * K + k0 + seg * 8];
                    float4 v1 = *(const float4*)&Af[(size_t)gr * K + k0 + seg * 8 + 4];
                    *(__half2*)&tmp[0] = __floats2half2_rn(v0.x, v0.y);
                    *(__half2*)&tmp[2] = __floats2half2_rn(v0.z, v0.w);
                    *(__half2*)&tmp[4] = __floats2half2_rn(v1.x, v1.y);
                    *(__half2*)&tmp[6] = __floats2half2_rn(v1.z, v1.w);
                } else {
                    #pragma unroll
                    for (int q = 0; q < 8; q++) tmp[q] = __float2half_rn(0.f);
                }
                *(uint4*)&As[row][seg * 8] = *(uint4*)tmp;
            } else {
                uint4 v = make_uint4(0u, 0u, 0u, 0u);
                if (gr < M) v = *(const uint4*)&Ah[(size_t)gr * K + k0 + seg * 8];
                *(uint4*)&As[row][seg * 8] = v;
            }
        }
        {
            int r = t >> 3, cseg = t & 7;
            uint4 v = *(const uint4*)&B[(size_t)(k0 + r) * Nn + cb + cseg * 8];
            const __half* hv = (const __half*)&v;
            #pragma unroll
            for (int j = 0; j < 8; j++) Bs[cseg * 8 + j][r] = hv[j];
        }
        __syncthreads();
        #pragma unroll
        for (int kk = 0; kk < 32; kk += 16) {
            int r0 = wid * 16 + g;
            uint32_t a0 = *(const uint32_t*)&As[r0    ][kk + tg * 2];
            uint32_t a1 = *(const uint32_t*)&As[r0 + 8][kk + tg * 2];
            uint32_t a2 = *(const uint32_t*)&As[r0    ][kk + tg * 2 + 8];
            uint32_t a3 = *(const uint32_t*)&As[r0 + 8][kk + tg * 2 + 8];
            #pragma unroll
            for (int nt = 0; nt < 8; nt++) {
                int c0 = nt * 8 + g;
                uint32_t b0 = *(const uint32_t*)&Bs[c0][kk + tg * 2];
                uint32_t b1 = *(const uint32_t*)&Bs[c0][kk + tg * 2 + 8];
                mma16816(acc[nt], a0, a1, a2, a3, b0, b1);
            }
        }
        __syncthreads();
    }

    #pragma unroll
    for (int rv = 0; rv < 2; rv++) {
        int row = rb + wid * 16 + g + rv * 8;
        bool ok = row < M;
        float sp = 0.f, dp = 0.f;
        #pragma unroll
        for (int nt = 0; nt < 8; nt++) {
            int col = nt * 8 + tg * 2;
            float cx = acc[nt][rv * 2 + 0];
            float cy = acc[nt][rv * 2 + 1];
            if (ok)
                *(__half2*)&Ch[(size_t)row * Nn + cb + col] = __floats2half2_rn(cx, cy);
            sp += cx * att_src[head * 64 + col] + cy * att_src[head * 64 + col + 1];
            dp += cx * att_dst[head * 64 + col] + cy * att_dst[head * 64 + col + 1];
        }
        sp += __shfl_xor_sync(0xffffffffu, sp, 1);
        sp += __shfl_xor_sync(0xffffffffu, sp, 2);
        dp += __shfl_xor_sync(0xffffffffu, dp, 1);
        dp += __shfl_xor_sync(0xffffffffu, dp, 2);
        if (tg == 0 && ok) {
            as_[row * HEADS + head] = sp;
            ad_[row * HEADS + head] = dp;
        }
    }
}

// ---------------- single-pass softmax: write exp(e), accumulate sums -----------
// No max-subtraction: |e| is O(10) for this model, exp() safe in fp32.
template<int HHEADS>
__global__ void stats_kernel(const float* __restrict__ as_, const float* __restrict__ ad_,
                             float* __restrict__ wout, float* __restrict__ inv_) {
    int w = (blockIdx.x * blockDim.x + threadIdx.x) >> 5;
    if (w >= NN) return;
    int lane = threadIdx.x & 31;
    int s0 = g_rowptr[w], s1 = g_rowptr[w + 1];
    float ad[HHEADS], sum[HHEADS];
    #pragma unroll
    for (int h = 0; h < HHEADS; h++) { ad[h] = ad_[w * HHEADS + h]; sum[h] = 0.f; }
    for (int j = s0 + lane; j < s1; j += 32) {
        int s = g_colsrc[j];
        if (HHEADS == 4) {
            float4 v = *(const float4*)&as_[(size_t)s * 4];
            float av[4] = {v.x, v.y, v.z, v.w};
            float wv[4];
            #pragma unroll
            for (int h = 0; h < 4; h++) {
                float e = av[h] + ad[h];
                e = e >= 0.f ? e : NEG_SLOPE * e;
                wv[h] = __expf(e);
                sum[h] += wv[h];
            }
            *(float4*)&wout[(size_t)j * 4] = make_float4(wv[0], wv[1], wv[2], wv[3]);
        } else {
            float e = as_[s] + ad[0];
            e = e >= 0.f ? e : NEG_SLOPE * e;
            float ex = __expf(e);
            wout[j] = ex;
            sum[0] += ex;
        }
    }
    #pragma unroll
    for (int h = 0; h < HHEADS; h++)
        #pragma unroll
        for (int off = 16; off; off >>= 1)
            sum[h] += __shfl_xor_sync(0xffffffffu, sum[h], off);
    if (!lane) {
        #pragma unroll
        for (int h = 0; h < HHEADS; h++)
            inv_[w * HHEADS + h] = 1.0f / (sum[h] + 1e-16f);
    }
}

// ---------------- agg1: ONE warp per dst, uint4 (8-half) lanes -----------------
__global__ __launch_bounds__(256) void agg1_kernel(
        const __half* __restrict__ xwh, const float* __restrict__ wtab,
        const float* __restrict__ inv_,
        const float* __restrict__ bias,
        const float* __restrict__ bng, const float* __restrict__ bnb,
        const float* __restrict__ bnm, const float* __restrict__ bnv,
        __half* __restrict__ hout) {
    int d = (blockIdx.x * 256 + threadIdx.x) >> 5;
    if (d >= NN) return;
    int lane = threadIdx.x & 31;
    int q = lane >> 3;                 // head index (lane group of 8 covers 64 cols)
    int colbase = lane * 8;
    int s0 = g_rowptr[d], s1 = g_rowptr[d + 1];
    const __half* bp = xwh + colbase;

    float acc[8] = {};
    int j = s0;
    for (; j + 2 <= s1; j += 2) {
        int sa = g_colsrc[j], sb = g_colsrc[j + 1];
        float wa = wtab[(size_t)j * 4 + q];
        float wb = wtab[(size_t)(j + 1) * 4 + q];
        uint4 ra = *(const uint4*)(bp + (size_t)sa * F1);
        uint4 rb = *(const uint4*)(bp + (size_t)sb * F1);
        const __half2* ha = (const __half2*)&ra;
        const __half2* hb = (const __half2*)&rb;
        #pragma unroll
        for (int k = 0; k < 4; k++) {
            float2 fa = __half22float2(ha[k]);
            float2 fb = __half22float2(hb[k]);
            acc[2 * k]     += wa * fa.x + wb * fb.x;
            acc[2 * k + 1] += wa * fa.y + wb * fb.y;
        }
    }
    if (j < s1) {
        int s = g_colsrc[j];
        float w = wtab[(size_t)j * 4 + q];
        uint4 r = *(const uint4*)(bp + (size_t)s * F1);
        const __half2* hr = (const __half2*)&r;
        #pragma unroll
        for (int k = 0; k < 4; k++) {
            float2 f = __half22float2(hr[k]);
            acc[2 * k]     += w * f.x;
            acc[2 * k + 1] += w * f.y;
        }
    }

    float inv = inv_[d * HH1 + q];
    __half outv[8];
    #pragma unroll
    for (int k = 0; k < 8; k += 4) {
        float4 bi = *(const float4*)&bias[colbase + k];
        float4 bm = *(const float4*)&bnm[colbase + k];
        float4 bg = *(const float4*)&bng[colbase + k];
        float4 bv = *(const float4*)&bnv[colbase + k];
        float4 bb = *(const float4*)&bnb[colbase + k];
        float o0 = (acc[k]     * inv + bi.x - bm.x) * (bg.x * rsqrtf(bv.x + BN_EPS)) + bb.x;
        float o1 = (acc[k + 1] * inv + bi.y - bm.y) * (bg.y * rsqrtf(bv.y + BN_EPS)) + bb.y;
        float o2 = (acc[k + 2] * inv + bi.z - bm.z) * (bg.z * rsqrtf(bv.z + BN_EPS)) + bb.z;
        float o3 = (acc[k + 3] * inv + bi.w - bm.w) * (bg.w * rsqrtf(bv.w + BN_EPS)) + bb.w;
        *(__half2*)&outv[k]     = __floats2half2_rn(fmaxf(o0, 0.f), fmaxf(o1, 0.f));
        *(__half2*)&outv[k + 2] = __floats2half2_rn(fmaxf(o2, 0.f), fmaxf(o3, 0.f));
    }
    *(uint4*)&hout[(size_t)d * F1 + colbase] = *(uint4*)outv;
}

// ---------------- agg2: warp per dst + fused pooling ---------------------------
__global__ __launch_bounds__(256) void agg2_kernel(
        const __half* __restrict__ xwh, const float* __restrict__ wtab,
        const float* __restrict__ inv_,
        const float* __restrict__ bias,
        const float* __restrict__ bng, const float* __restrict__ bnb,
        const float* __restrict__ bnm, const float* __restrict__ bnv,
        const int* __restrict__ batch) {
    int d = (blockIdx.x * 256 + threadIdx.x) >> 5;
    if (d >= NN) return;
    int lane = threadIdx.x & 31;
    int s0 = g_rowptr[d], s1 = g_rowptr[d + 1];
    const __half* bp = xwh + lane * 2;
    float ax = 0.f, ay = 0.f;
    int j = s0;
    for (; j + 4 <= s1; j += 4) {
        int sa = g_colsrc[j], sb = g_colsrc[j + 1], sc = g_colsrc[j + 2], sd = g_colsrc[j + 3];
        float wa = wtab[j], wb = wtab[j + 1], wc = wtab[j + 2], wd = wtab[j + 3];
        float2 va = __half22float2(*(const __half2*)(bp + (size_t)sa * F2));
        float2 vb = __half22float2(*(const __half2*)(bp + (size_t)sb * F2));
        float2 vc = __half22float2(*(const __half2*)(bp + (size_t)sc * F2));
        float2 vd = __half22float2(*(const __half2*)(bp + (size_t)sd * F2));
        ax += wa * va.x + wb * vb.x + wc * vc.x + wd * vd.x;
        ay += wa * va.y + wb * vb.y + wc * vc.y + wd * vd.y;
    }
    for (; j < s1; j++) {
        int s = g_colsrc[j];
        float w = wtab[j];
        float2 v = __half22float2(*(const __half2*)(bp + (size_t)s * F2));
        ax += w * v.x;
        ay += w * v.y;
    }
    float inv = inv_[d];
    ax *= inv; ay *= inv;
    int col = lane * 2;
    float2 bi = *(const float2*)&bias[col];
    float2 bm = *(const float2*)&bnm[col];
    float2 bg = *(const float2*)&bng[col];
    float2 bv = *(const float2*)&bnv[col];
    float2 bb = *(const float2*)&bnb[col];
    float o0 = (ax + bi.x - bm.x) * (bg.x * rsqrtf(bv.x + BN_EPS)) + bb.x;
    float o1 = (ay + bi.y - bm.y) * (bg.y * rsqrtf(bv.y + BN_EPS)) + bb.y;
    o0 = fmaxf(o0, 0.f);
    o1 = fmaxf(o1, 0.f);
    int g = batch[d];
    atomicAdd(&g_gsum[g * F2 + col],     o0);
    atomicAdd(&g_gsum[g * F2 + col + 1], o1);
}

// ---------------- classifier head + log_softmax ----------------
__global__ void head_kernel(const float* __restrict__ Wc1, const float* __restrict__ bc1,
                            const float* __restrict__ Wc2, const float* __restrict__ bc2,
                            float* __restrict__ out) {
    __shared__ float repr[64];
    __shared__ float hc[64];
    __shared__ float logit[2];
    int g = blockIdx.x, j = threadIdx.x;
    float inv = 1.f / fmaxf(g_gcnt[g], 1.f);
    repr[j] = g_gsum[g * 64 + j] * inv;
    __syncthreads();
    float a = bc1[j];
    #pragma unroll
    for (int k = 0; k < 64; k++) a += repr[k] * Wc1[k * 64 + j];
    hc[j] = fmaxf(a, 0.f);
    __syncthreads();
    if (j < 2) {
        float l = bc2[j];
        for (int k = 0; k < 64; k++) l += hc[k] * Wc2[k * 2 + j];
        logit[j] = l;
    }
    __syncthreads();
    if (j == 0) {
        float l0 = logit[0], l1 = logit[1];
        float mx = fmaxf(l0, l1);
        float lse = mx + logf(expf(l0 - mx) + expf(l1 - mx));
        out[g * 2 + 0] = l0 - lse;
        out[g * 2 + 1] = l1 - lse;
    }
}

// ---------------- launch ----------------
extern "C" void kernel_launch(void* const* d_in, const int* in_sizes, int n_in,
                              void* d_out, int out_size) {
    const float* x        = (const float*)d_in[0];
    const int*   ei       = (const int*)  d_in[1];
    const int*   batch    = (const int*)  d_in[2];
    const float* W1       = (const float*)d_in[3];
    const float* att_src1 = (const float*)d_in[4];
    const float* att_dst1 = (const float*)d_in[5];
    const float* bias1    = (const float*)d_in[6];
    const float* bn1_g    = (const float*)d_in[7];
    const float* bn1_b    = (const float*)d_in[8];
    const float* bn1_m    = (const float*)d_in[9];
    const float* bn1_v    = (const float*)d_in[10];
    const float* W2       = (const float*)d_in[11];
    const float* att_src2 = (const float*)d_in[12];
    const float* att_dst2 = (const float*)d_in[13];
    const float* bias2    = (const float*)d_in[14];
    const float* bn2_g    = (const float*)d_in[15];
    const float* bn2_b    = (const float*)d_in[16];
    const float* bn2_m    = (const float*)d_in[17];
    const float* bn2_v    = (const float*)d_in[18];
    const float* Wc1      = (const float*)d_in[19];
    const float* bc1      = (const float*)d_in[20];
    const float* Wc2      = (const float*)d_in[21];
    const float* bc2      = (const float*)d_in[22];
    float* out = (float*)d_out;

    __half *p_W1h, *p_W2h, *p_xw1h, *p_h1h, *p_xw2h;
    cudaGetSymbolAddress((void**)&p_W1h,  g_W1h);
    cudaGetSymbolAddress((void**)&p_W2h,  g_W2h);
    cudaGetSymbolAddress((void**)&p_xw1h, g_xw1h);
    cudaGetSymbolAddress((void**)&p_h1h,  g_h1h);
    cudaGetSymbolAddress((void**)&p_xw2h, g_xw2h);
    float *p_as1, *p_ad1, *p_as2, *p_ad2, *p_w1, *p_w2, *p_inv1, *p_inv2;
    cudaGetSymbolAddress((void**)&p_as1,  g_as1);
    cudaGetSymbolAddress((void**)&p_ad1,  g_ad1);
    cudaGetSymbolAddress((void**)&p_as2,  g_as2);
    cudaGetSymbolAddress((void**)&p_ad2,  g_ad2);
    cudaGetSymbolAddress((void**)&p_w1,   g_w1);
    cudaGetSymbolAddress((void**)&p_w2,   g_w2);
    cudaGetSymbolAddress((void**)&p_inv1, g_inv1);
    cudaGetSymbolAddress((void**)&p_inv2, g_inv2);

    // CSR build + init
    init_kernel<<<(NN + 255) / 256, 256>>>();
    count_kernel<<<(EE + 255) / 256, 256>>>(ei, batch);
    scan_kernel<<<1, 1024>>>();
    fill_kernel<<<(EP + 255) / 256, 256>>>(ei);

    // fp16 conversions (weights only; x converted inline in hgemm1)
    f2h_kernel<<<(DIN * F1 / 4 + 255) / 256, 256>>>(W1, p_W1h, DIN * F1 / 4);
    f2h_kernel<<<(F1 * F2 / 4 + 255) / 256, 256>>>(W2,  p_W2h, F1 * F2 / 4);

    const int MB = (NN + 127) / 128;   // 391

    // ---- layer 1 ----
    hgemm_kernel<HH1, true><<<dim3(F1 / 64, MB), 256>>>(
        x, p_W1h, p_xw1h, att_src1, att_dst1, p_as1, p_ad1, NN, F1, DIN);
    stats_kernel<HH1><<<(NN * 32 + 255) / 256, 256>>>(p_as1, p_ad1, p_w1, p_inv1);
    agg1_kernel<<<(NN * 32 + 255) / 256, 256>>>(
        p_xw1h, p_w1, p_inv1, bias1, bn1_g, bn1_b, bn1_m, bn1_v, p_h1h);

    // ---- layer 2 ----
    hgemm_kernel<1, false><<<dim3(F2 / 64, MB), 256>>>(
        p_h1h, p_W2h, p_xw2h, att_src2, att_dst2, p_as2, p_ad2, NN, F2, F1);
    stats_kernel<1><<<(NN * 32 + 255) / 256, 256>>>(p_as2, p_ad2, p_w2, p_inv2);
    agg2_kernel<<<(NN * 32 + 255) / 256, 256>>>(
        p_xw2h, p_w2, p_inv2, bias2, bn2_g, bn2_b, bn2_m, bn2_v, batch);

    // ---- classifier ----
    head_kernel<<<GG, 64>>>(Wc1, bc1, Wc2, bc2, out);
}